// round 13
// baseline (speedup 1.0000x reference)
#include <cuda_runtime.h>
#include <math.h>

// ---------------------------------------------------------------------------
// Problem dims
// ---------------------------------------------------------------------------
#define NBLK   148
#define NTHR   512
#define GSTRIDE (NBLK * NTHR)
#define Bz     128
#define Sz     512
#define Hz     1024
#define MIDz   512
#define FEATz  576
#define G4Hz   4096
#define KC     16

// Output layout: outs[B,S,H], h2f[1,B,H], c2f[1,B,H], flags[S]
#define OUT_H2    67108864
#define OUT_C2    67239936
#define OUT_FLAGS 67371008

typedef unsigned long long ull;

// ---------------------------------------------------------------------------
// Device-global scratch (allocation-free per harness rules)
// ---------------------------------------------------------------------------
__device__ __align__(16) float g_embeds[(size_t)Sz * Bz * FEATz];   // [t][b][f]
__device__ __align__(16) float g_mx1all[(size_t)Sz * Bz * Hz];      // X@Wmx1^T
__device__ __align__(16) float g_zx1all[(size_t)Sz * Bz * G4Hz];    // X@Wih1^T
__device__ __align__(16) float g_zbxv[Sz * Bz];                     // x·u + bdvs
__device__ __align__(16) float g_u[FEATz];                          // Wsi^T vs
__device__ __align__(16) float g_wv[Hz];                            // Wsh^T vs
__device__ float g_bdvs;

__device__ __align__(16) float g_h1[Bz * Hz];
__device__ __align__(16) float g_c1[Bz * Hz];
__device__ __align__(16) float g_h2[Bz * Hz];
__device__ __align__(16) float g_c2[Bz * Hz];
__device__ __align__(16) float g_x2[Bz * Hz];
__device__ __align__(16) float g_mh1p[4][Bz * Hz];
__device__ __align__(16) float g_p1p[2][Bz * G4Hz];
__device__ __align__(16) float g_mx2p[3][Bz * Hz];
__device__ __align__(16) float g_mh2p[3][Bz * Hz];
__device__ __align__(16) float g_zx2p[3][Bz * G4Hz];
__device__ __align__(16) float g_p2p[2][Bz * G4Hz];
__device__ __align__(16) float g_s[Bz];

// grid barrier state (zero-init; gen compared relatively, replay-safe)
__device__ unsigned g_bar_cnt;
__device__ volatile unsigned g_bar_gen;

__device__ __forceinline__ void gridbar() {
    __threadfence();               // release
    __syncthreads();
    if (threadIdx.x == 0) {
        unsigned gen = g_bar_gen;
        if (atomicAdd(&g_bar_cnt, 1u) == (unsigned)(NBLK - 1)) {
            g_bar_cnt = 0u;
            __threadfence();
            g_bar_gen = gen + 1u;
        } else {
            while (g_bar_gen == gen) { __nanosleep(32); }
        }
    }
    __syncthreads();
    __threadfence();               // acquire (CCTL.IVALL flushes L1D)
}

// ---------------------------------------------------------------------------
// Packed f32x2 FMA (Blackwell; PTX required)
// ---------------------------------------------------------------------------
__device__ __forceinline__ void ffma2(ull &acc, ull a, ull b) {
    asm("fma.rn.f32x2 %0, %1, %2, %0;" : "+l"(acc) : "l"(a), "l"(b));
}
__device__ __forceinline__ float sigm(float x) { return 1.0f / (1.0f + expf(-x)); }

// ---------------------------------------------------------------------------
// fp32 GEMM tile, 512 threads: C[0:MROWS, 0:64] = A[MROWS,K] @ W[0:64,K]^T
//   A-operand = (sum_{j<NA} Ap[j]) * (NM ? sum_{j<NM} Mp[j] : 1)
// Column-pair f32x2 accumulators; A stored PRE-DUPLICATED in smem so the
// inner loop is 3 LDS + 8(or 4) FFMA2 per k — zero MOVs.
// ---------------------------------------------------------------------------
template<int MROWS, int NA, int NM>
__device__ __forceinline__ void gemm_tile(
    const float* const* Ap, const float* const* Mp, int lda,
    const float* __restrict__ W, int ldw, int K,
    float* __restrict__ C, int ldc,
    float (*As2)[KC][260], float (*Ws)[KC][68])
{
    constexpr int NP = MROWS / 64;           // rows per thread (2 or 1)
    const int tid = threadIdx.x;
    const int tx8 = (tid & 7) * 8;           // col base (8 cols)
    const int ty  = tid >> 3;                // 0..63

    ull acc[NP][4];
#pragma unroll
    for (int i = 0; i < NP; i++)
#pragma unroll
        for (int j = 0; j < 4; j++) acc[i][j] = 0ull;

    const bool stager = (MROWS == 128) || (tid < 256);
    const int sr = tid >> 2;                 // staging row
    const int skq = (tid & 3) * 4;           // staging k offset

    float4 arA[NA];
    float4 arM[(NM > 0) ? NM : 1];
    float4 wr;

    auto loadA = [&](int k0) {
        if (stager) {
            size_t off = (size_t)sr * lda + k0 + skq;
#pragma unroll
            for (int j = 0; j < NA; j++) arA[j] = *(const float4*)(Ap[j] + off);
            if constexpr (NM > 0) {
#pragma unroll
                for (int j = 0; j < NM; j++) arM[j] = *(const float4*)(Mp[j] + off);
            }
        }
    };
    auto loadW = [&](int k0) {
        if (tid < 256)
            wr = *(const float4*)(W + (size_t)sr * ldw + k0 + skq);
    };

    loadA(0); loadW(0);

    const int nc = K / KC;
    int buf = 0;
    for (int c = 0; c < nc; c++) {
        // stage regs -> smem[buf]
        if (stager) {
            float4 v = arA[0];
#pragma unroll
            for (int j = 1; j < NA; j++) {
                v.x += arA[j].x; v.y += arA[j].y; v.z += arA[j].z; v.w += arA[j].w;
            }
            if constexpr (NM > 0) {
                float4 m = arM[0];
#pragma unroll
                for (int j = 1; j < NM; j++) {
                    m.x += arM[j].x; m.y += arM[j].y; m.z += arM[j].z; m.w += arM[j].w;
                }
                v.x *= m.x; v.y *= m.y; v.z *= m.z; v.w *= m.w;
            }
            int r2 = sr * 2;
            As2[buf][skq + 0][r2] = v.x; As2[buf][skq + 0][r2 + 1] = v.x;
            As2[buf][skq + 1][r2] = v.y; As2[buf][skq + 1][r2 + 1] = v.y;
            As2[buf][skq + 2][r2] = v.z; As2[buf][skq + 2][r2 + 1] = v.z;
            As2[buf][skq + 3][r2] = v.w; As2[buf][skq + 3][r2 + 1] = v.w;
        }
        if (tid < 256) {
            Ws[buf][skq + 0][sr] = wr.x; Ws[buf][skq + 1][sr] = wr.y;
            Ws[buf][skq + 2][sr] = wr.z; Ws[buf][skq + 3][sr] = wr.w;
        }
        __syncthreads();

        if (c + 1 < nc) { loadA((c + 1) * KC); loadW((c + 1) * KC); }  // prefetch

#pragma unroll
        for (int k = 0; k < KC; k++) {
            ulonglong2 b01 = *(const ulonglong2*)&Ws[buf][k][tx8];
            ulonglong2 b23 = *(const ulonglong2*)&Ws[buf][k][tx8 + 4];
            if constexpr (NP == 2) {
                ulonglong2 av = *(const ulonglong2*)&As2[buf][k][4 * ty];
                ffma2(acc[0][0], av.x, b01.x); ffma2(acc[0][1], av.x, b01.y);
                ffma2(acc[0][2], av.x, b23.x); ffma2(acc[0][3], av.x, b23.y);
                ffma2(acc[1][0], av.y, b01.x); ffma2(acc[1][1], av.y, b01.y);
                ffma2(acc[1][2], av.y, b23.x); ffma2(acc[1][3], av.y, b23.y);
            } else {
                ull av = *(const ull*)&As2[buf][k][2 * ty];
                ffma2(acc[0][0], av, b01.x); ffma2(acc[0][1], av, b01.y);
                ffma2(acc[0][2], av, b23.x); ffma2(acc[0][3], av, b23.y);
            }
        }
        buf ^= 1;
    }
    __syncthreads();   // protect smem before caller's next gemm_tile

    // epilogue: acc[i][j] = cols (tx8+2j, tx8+2j+1) of row (ty*NP + i)
#pragma unroll
    for (int i = 0; i < NP; i++) {
        int m = ty * NP + i;
#pragma unroll
        for (int j = 0; j < 4; j++) {
            float lo = __uint_as_float((unsigned int)(acc[i][j] & 0xffffffffull));
            float hi = __uint_as_float((unsigned int)(acc[i][j] >> 32));
            C[(size_t)m * ldc + tx8 + 2 * j]     = lo;
            C[(size_t)m * ldc + tx8 + 2 * j + 1] = hi;
        }
    }
}

// ---------------------------------------------------------------------------
// The persistent kernel
// ---------------------------------------------------------------------------
__global__ __launch_bounds__(NTHR, 1) void enc_persistent(
    const int* __restrict__ ids, const int* __restrict__ xids,
    const float* __restrict__ wemb, const float* __restrict__ xemb,
    const float* __restrict__ Wsi, const float* __restrict__ Wsh,
    const float* __restrict__ b_bd, const float* __restrict__ vs,
    const float* __restrict__ Wmx1, const float* __restrict__ Wmh1,
    const float* __restrict__ Wih1, const float* __restrict__ Whh1,
    const float* __restrict__ b1,
    const float* __restrict__ Wmx2, const float* __restrict__ Wmh2,
    const float* __restrict__ Wih2, const float* __restrict__ Whh2,
    const float* __restrict__ b2,
    float* __restrict__ out)
{
    __shared__ float As2[2][KC][260];
    __shared__ float Ws[2][KC][68];
    __shared__ float red[16];

    const int blk = blockIdx.x;
    const int tid = threadIdx.x;
    const int gtid = blk * NTHR + tid;
    const int wid = tid >> 5, lane = tid & 31;
    const int gwarp = blk * (NTHR / 32) + wid;     // global warp id

    // ================= Prologue P1: states, u/wv/bdvs, embeds =================
    for (int i = gtid; i < Bz * Hz; i += GSTRIDE) {
        g_h1[i] = 0.0f; g_c1[i] = 0.0f; g_h2[i] = 0.0f; g_c2[i] = 0.0f;
    }
    // u[f] = sum_m Wsi[m][f]*vs[m]  (warp per f), wv[h] likewise
    for (int f = gwarp; f < FEATz; f += NBLK * 16) {
        float s = 0.0f;
        for (int m = lane; m < MIDz; m += 32) s += Wsi[(size_t)m * FEATz + f] * vs[m];
#pragma unroll
        for (int o = 16; o; o >>= 1) s += __shfl_xor_sync(~0u, s, o);
        if (lane == 0) g_u[f] = s;
    }
    for (int h = gwarp - NBLK * 16 + Hz * 0; 0; ) break;  // (no-op guard)
    for (int h = gwarp; h < Hz; h += NBLK * 16) {
        // use a different offset range so both run; cheap enough to double-assign
        float s = 0.0f;
        for (int m = lane; m < MIDz; m += 32) s += Wsh[(size_t)m * Hz + h] * vs[m];
#pragma unroll
        for (int o = 16; o; o >>= 1) s += __shfl_xor_sync(~0u, s, o);
        if (lane == 0) g_wv[h] = s;
    }
    if (blk == 0) {
        float sb = b_bd[tid] * vs[tid];   // MIDz == NTHR == 512
#pragma unroll
        for (int o = 16; o; o >>= 1) sb += __shfl_xor_sync(~0u, sb, o);
        if (lane == 0) red[wid] = sb;
        __syncthreads();
        if (tid == 0) {
            float s = 0.0f;
            for (int w = 0; w < 16; w++) s += red[w];
            g_bdvs = s;
        }
        __syncthreads();
    }
    {   // embed gather, float4 granularity (576 = 144 float4)
        const int Q = FEATz / 4;
        for (int i = gtid; i < Sz * Bz * Q; i += GSTRIDE) {
            int q = i % Q;
            int row = i / Q;
            int b = row & (Bz - 1);
            int t = row >> 7;
            int f = q * 4;
            float4 v;
            if (f < 512) v = *(const float4*)(wemb + (size_t)ids[b * Sz + t] * 512 + f);
            else         v = *(const float4*)(xemb + (size_t)xids[b * Sz + t] * 64 + (f - 512));
            *(float4*)(g_embeds + (size_t)row * FEATz + f) = v;
        }
    }
    gridbar();

    // ================= Prologue P2: zbxv + all x-dependent GEMMs ==============
    {   // zbxv[r] = embeds_row · u + bdvs (warp per row)
        float bdv = g_bdvs;
        for (int r = gwarp; r < Sz * Bz; r += NBLK * 16) {
            const float* e = g_embeds + (size_t)r * FEATz;
            float s = 0.0f;
            for (int j = lane; j < FEATz; j += 32) s += e[j] * g_u[j];
#pragma unroll
            for (int o = 16; o; o >>= 1) s += __shfl_xor_sync(~0u, s, o);
            if (lane == 0) g_zbxv[r] = s + bdv;
        }
    }
    // 512 * (16 + 64) = 40960 GEMM items, K=576
    for (int it = blk; it < 40960; it += NBLK) {
        int t = it / 80, j = it % 80;
        const float* Aa[1] = { g_embeds + (size_t)t * Bz * FEATz };
        if (j < 16)
            gemm_tile<128, 1, 0>(Aa, nullptr, FEATz,
                Wmx1 + (size_t)j * 64 * FEATz, FEATz, FEATz,
                g_mx1all + (size_t)t * Bz * Hz + j * 64, Hz, As2, Ws);
        else
            gemm_tile<128, 1, 0>(Aa, nullptr, FEATz,
                Wih1 + (size_t)(j - 16) * 64 * FEATz, FEATz, FEATz,
                g_zx1all + (size_t)t * Bz * G4Hz + (j - 16) * 64, G4Hz, As2, Ws);
    }
    gridbar();

    // ============================ time loop ===================================
    for (int t = 0; t < Sz; t++) {

        // ---- Phase A': mh1 partials (64-row, K-split 4) + boundary s ----
        if (blk < 128) {
            // item: tile(16) x rowhalf(2) x kseg(4)
            int tile = blk >> 3;
            int mh = (blk >> 2) & 1, ks = blk & 3, ko = ks * 256;
            const float* Aa[1] = { g_h1 + (size_t)mh * 64 * Hz + ko };
            gemm_tile<64, 1, 0>(Aa, nullptr, Hz,
                Wmh1 + (size_t)tile * 64 * Hz + ko, Hz, 256,
                g_mh1p[ks] + (size_t)mh * 64 * Hz + tile * 64, Hz, As2, Ws);
        } else {
            // boundary: warp per row. 20 blocks x 16 warps = 320 >= 128 rows
            int r = (blk - 128) * 16 + wid;
            if (r < Bz) {
                const float* h1r = g_h1 + (size_t)r * Hz;
                float s = 0.0f;
#pragma unroll
                for (int i = 0; i < Hz / 32; i++) s += h1r[lane + 32 * i] * g_wv[lane + 32 * i];
#pragma unroll
                for (int o = 16; o; o >>= 1) s += __shfl_xor_sync(~0u, s, o);
                if (lane == 0)
                    g_s[r] = (s + g_zbxv[t * Bz + r] > 0.0f) ? 1.0f : 0.0f;
            }
        }
        gridbar();

        const float flag = g_s[0];
        const bool doflag = (flag > 0.5f);
        if (blk == 0 && tid == 0) out[OUT_FLAGS + t] = flag;

        // ---- Phase B: p1 = (mx1all[t] .* Σmh1p) @ Whh1^T ----
        if (blk < 128) {
            int tile = blk >> 1, half = blk & 1, ko = half * 512;
            const float* Aa[1] = { g_mx1all + (size_t)t * Bz * Hz + ko };
            const float* Mp[4] = { g_mh1p[0] + ko, g_mh1p[1] + ko,
                                   g_mh1p[2] + ko, g_mh1p[3] + ko };
            gemm_tile<128, 1, 4>(Aa, Mp, Hz,
                Whh1 + (size_t)tile * 64 * Hz + ko, Hz, 512,
                g_p1p[half] + tile * 64, G4Hz, As2, Ws);
        }
        gridbar();

        // ---- Phase C: gates1 (+ output write when flag==0) ----
        {
            const float* zx1 = g_zx1all + (size_t)t * Bz * G4Hz;
            for (int idx = gtid; idx < Bz * Hz; idx += GSTRIDE) {
                int b = idx >> 10, h = idx & (Hz - 1);
                size_t zi = (size_t)b * G4Hz + h;
                float vi = zx1[zi]          + b1[h]          + g_p1p[0][zi]          + g_p1p[1][zi];
                float vf = zx1[zi + Hz]     + b1[h + Hz]     + g_p1p[0][zi + Hz]     + g_p1p[1][zi + Hz];
                float vg = zx1[zi + 2*Hz]   + b1[h + 2*Hz]   + g_p1p[0][zi + 2*Hz]   + g_p1p[1][zi + 2*Hz];
                float vo = zx1[zi + 3*Hz]   + b1[h + 3*Hz]   + g_p1p[0][zi + 3*Hz]   + g_p1p[1][zi + 3*Hz];
                float c  = sigm(vf) * g_c1[idx] + sigm(vi) * tanhf(vg);
                float hn = sigm(vo) * tanhf(c);
                float sv = g_s[b];
                g_x2[idx] = hn * sv;
                g_h1[idx] = hn * (1.0f - sv);
                g_c1[idx] = c  * (1.0f - sv);
                if (!doflag)
                    out[(size_t)b * Sz * Hz + (size_t)t * Hz + h] = g_h2[idx];
            }
        }
        gridbar();   // end of C (end of step when flag==0)

        if (!doflag) continue;   // uniform across all blocks

        // ---- Phase D: mx2, zx2, mh2 (K split 352/336/336): 288 items ----
        for (int it2 = blk; it2 < 288; it2 += NBLK) {
            int tile = it2 / 3, seg = it2 % 3;
            int ko = (seg == 0) ? 0 : (seg == 1 ? 352 : 688);
            int kl = (seg == 0) ? 352 : 336;
            const float* Aa[1];
            if (tile < 16) {
                Aa[0] = g_x2 + ko;
                gemm_tile<128, 1, 0>(Aa, nullptr, Hz,
                    Wmx2 + (size_t)tile * 64 * Hz + ko, Hz, kl,
                    g_mx2p[seg] + tile * 64, Hz, As2, Ws);
            } else if (tile < 80) {
                int z = tile - 16;
                Aa[0] = g_x2 + ko;
                gemm_tile<128, 1, 0>(Aa, nullptr, Hz,
                    Wih2 + (size_t)z * 64 * Hz + ko, Hz, kl,
                    g_zx2p[seg] + z * 64, G4Hz, As2, Ws);
            } else {
                int m2 = tile - 80;
                Aa[0] = g_h2 + ko;
                gemm_tile<128, 1, 0>(Aa, nullptr, Hz,
                    Wmh2 + (size_t)m2 * 64 * Hz + ko, Hz, kl,
                    g_mh2p[seg] + m2 * 64, Hz, As2, Ws);
            }
        }
        gridbar();

        // ---- Phase E: p2 = ((Σmx2p) .* (Σmh2p)) @ Whh2^T ----
        if (blk < 128) {
            int tile = blk >> 1, half = blk & 1, ko = half * 512;
            const float* Aa[3] = { g_mx2p[0] + ko, g_mx2p[1] + ko, g_mx2p[2] + ko };
            const float* Mp[3] = { g_mh2p[0] + ko, g_mh2p[1] + ko, g_mh2p[2] + ko };
            gemm_tile<128, 3, 3>(Aa, Mp, Hz,
                Whh2 + (size_t)tile * 64 * Hz + ko, Hz, 512,
                g_p2p[half] + tile * 64, G4Hz, As2, Ws);
        }
        gridbar();

        // ---- Phase F: gates2 + state update + output write ----
        for (int idx = gtid; idx < Bz * Hz; idx += GSTRIDE) {
            int b = idx >> 10, h = idx & (Hz - 1);
            size_t zi = (size_t)b * G4Hz + h;
            float vi = g_zx2p[0][zi]          + g_zx2p[1][zi]          + g_zx2p[2][zi]
                     + b2[h]                  + g_p2p[0][zi]           + g_p2p[1][zi];
            float vf = g_zx2p[0][zi + Hz]     + g_zx2p[1][zi + Hz]     + g_zx2p[2][zi + Hz]
                     + b2[h + Hz]             + g_p2p[0][zi + Hz]      + g_p2p[1][zi + Hz];
            float vg = g_zx2p[0][zi + 2*Hz]   + g_zx2p[1][zi + 2*Hz]   + g_zx2p[2][zi + 2*Hz]
                     + b2[h + 2*Hz]           + g_p2p[0][zi + 2*Hz]    + g_p2p[1][zi + 2*Hz];
            float vo = g_zx2p[0][zi + 3*Hz]   + g_zx2p[1][zi + 3*Hz]   + g_zx2p[2][zi + 3*Hz]
                     + b2[h + 3*Hz]           + g_p2p[0][zi + 3*Hz]    + g_p2p[1][zi + 3*Hz];
            float c  = sigm(vf) * g_c2[idx] + sigm(vi) * tanhf(vg);
            float hn = sigm(vo) * tanhf(c);
            g_c2[idx] = c;
            g_h2[idx] = hn;
            out[(size_t)b * Sz * Hz + (size_t)t * Hz + h] = hn;
        }
        gridbar();
    }

    // ---------------- final state outputs ----------------
    for (int i = gtid; i < Bz * Hz; i += GSTRIDE) {
        out[OUT_H2 + i] = g_h2[i];
        out[OUT_C2 + i] = g_c2[i];
    }
}

// ---------------------------------------------------------------------------
// Launch: ONE kernel node, graph-capturable
// ---------------------------------------------------------------------------
extern "C" void kernel_launch(void* const* d_in, const int* in_sizes, int n_in,
                              void* d_out, int out_size) {
    const int*   ids   = (const int*)d_in[0];
    const int*   xids  = (const int*)d_in[1];
    const float* wemb  = (const float*)d_in[2];
    const float* xemb  = (const float*)d_in[3];
    const float* Wsi   = (const float*)d_in[4];
    const float* Wsh   = (const float*)d_in[5];
    const float* b_bd  = (const float*)d_in[6];
    const float* vs    = (const float*)d_in[7];
    const float* Wmx1  = (const float*)d_in[8];
    const float* Wmh1  = (const float*)d_in[9];
    const float* Wih1  = (const float*)d_in[10];
    const float* Whh1  = (const float*)d_in[11];
    const float* b1    = (const float*)d_in[12];
    const float* Wmx2  = (const float*)d_in[13];
    const float* Wmh2  = (const float*)d_in[14];
    const float* Wih2  = (const float*)d_in[15];
    const float* Whh2  = (const float*)d_in[16];
    const float* b2    = (const float*)d_in[17];
    float* out = (float*)d_out;

    enc_persistent<<<NBLK, NTHR>>>(ids, xids, wemb, xemb,
                                   Wsi, Wsh, b_bd, vs,
                                   Wmx1, Wmh1, Wih1, Whh1, b1,
                                   Wmx2, Wmh2, Wih2, Whh2, b2,
                                   out);
}

// round 14
// speedup vs baseline: 2.3985x; 2.3985x over previous
#include <cuda_runtime.h>
#include <math.h>

// ---------------------------------------------------------------------------
// Problem dims
// ---------------------------------------------------------------------------
#define NBLK   148
#define NTHR   256
#define GSTRIDE (NBLK * NTHR)
#define Bz     128
#define Sz     512
#define Hz     1024
#define MIDz   512
#define FEATz  576
#define G4Hz   4096
#define KC     16

// Output layout: outs[B,S,H], h2f[1,B,H], c2f[1,B,H], flags[S]
#define OUT_H2    67108864
#define OUT_C2    67239936
#define OUT_FLAGS 67371008

typedef unsigned long long ull;

// Dynamic smem partition: As2 (dup A, ull) then Wsm (B, float)
// As2: 2 bufs x KC x 130 ull   = 33280 B
// Wsm: 2 bufs x KC x 132 float = 16896 B
#define AS2_BUFSTRIDE (KC * 130)     // in ull
#define WSM_BUFSTRIDE (KC * 132)     // in float
#define SMEM_DYN (2 * AS2_BUFSTRIDE * 8 + 2 * WSM_BUFSTRIDE * 4)

// ---------------------------------------------------------------------------
// Device-global scratch (allocation-free per harness rules)
// ---------------------------------------------------------------------------
__device__ __align__(16) float g_embeds[(size_t)Sz * Bz * FEATz];   // [t][b][f]
__device__ __align__(16) float g_mx1all[(size_t)Sz * Bz * Hz];      // X@Wmx1^T
__device__ __align__(16) float g_zx1all[(size_t)Sz * Bz * G4Hz];    // X@Wih1^T
__device__ __align__(16) float g_zbxv[Sz * Bz];                     // x·u + bdvs
__device__ __align__(16) float g_u[FEATz];                          // Wsi^T vs
__device__ __align__(16) float g_wv[Hz];                            // Wsh^T vs
__device__ float g_bdvs;

__device__ __align__(16) float g_h1[Bz * Hz];
__device__ __align__(16) float g_c1[Bz * Hz];
__device__ __align__(16) float g_h2[Bz * Hz];
__device__ __align__(16) float g_c2[Bz * Hz];
__device__ __align__(16) float g_x2[Bz * Hz];
__device__ __align__(16) float g_mh1p[8][Bz * Hz];
__device__ __align__(16) float g_p1p[4][Bz * G4Hz];
__device__ __align__(16) float g_mx2p[3][Bz * Hz];
__device__ __align__(16) float g_mh2p[3][Bz * Hz];
__device__ __align__(16) float g_zx2p[3][Bz * G4Hz];
__device__ __align__(16) float g_p2p[4][Bz * G4Hz];
__device__ __align__(16) float g_s[Bz];

// grid barrier state (zero-init; gen compared relatively, replay-safe)
__device__ unsigned g_bar_cnt;
__device__ volatile unsigned g_bar_gen;

__device__ __forceinline__ void gridbar() {
    __threadfence();               // release
    __syncthreads();
    if (threadIdx.x == 0) {
        unsigned gen = g_bar_gen;
        if (atomicAdd(&g_bar_cnt, 1u) == (unsigned)(NBLK - 1)) {
            g_bar_cnt = 0u;
            __threadfence();
            g_bar_gen = gen + 1u;
        } else {
            while (g_bar_gen == gen) { __nanosleep(32); }
        }
    }
    __syncthreads();
    __threadfence();               // acquire (CCTL.IVALL flushes L1D)
}

// ---------------------------------------------------------------------------
// Packed f32x2 helpers
// ---------------------------------------------------------------------------
__device__ __forceinline__ void ffma2(ull &acc, ull a, ull b) {
    asm("fma.rn.f32x2 %0, %1, %2, %0;" : "+l"(acc) : "l"(a), "l"(b));
}
__device__ __forceinline__ ull dup2(float x) {
    unsigned u = __float_as_uint(x);
    ull r;
    asm("mov.b64 %0, {%1, %1};" : "=l"(r) : "r"(u));
    return r;
}
__device__ __forceinline__ float sigm(float x) { return 1.0f / (1.0f + expf(-x)); }

// ---------------------------------------------------------------------------
// fp32 GEMM tile, 256 threads: C[0:128, 0:128] += nothing (writes) =
//     A[128,K] @ W[0:128, K]^T ;  A-operand = (Σ_{j<NA} Ap[j]) * (NM? Σ Mp[j] : 1)
// Layout: warp w -> rows 16w..16w+15 ; lane l -> cols 4l..4l+3.
// A pre-duplicated (f32x2) in smem -> broadcast LDS.128; B one LDS.128/lane,
// conflict-free. Inner loop: 9 LDS + 32 FFMA2 per k, zero MOVs.
// ---------------------------------------------------------------------------
template<int NA, int NM>
__device__ __forceinline__ void gemm128(
    const float* const* Ap, const float* const* Mp, int lda,
    const float* __restrict__ W, int ldw, int K,
    float* __restrict__ C, int ldc,
    ull* __restrict__ As2, float* __restrict__ Wsm)
{
    const int tid = threadIdx.x;
    const int w = tid >> 5, l = tid & 31;

    ull acc[16][2];
#pragma unroll
    for (int i = 0; i < 16; i++) { acc[i][0] = 0ull; acc[i][1] = 0ull; }

    const int sr0 = tid >> 2;            // staging row/col base (0..63)
    const int skq = (tid & 3) * 4;       // staging k offset

    float4 pA[2][NA];
    float4 pM[2][(NM > 0) ? NM : 1];
    float4 pW[2];

    auto loadAB = [&](int k0) {
#pragma unroll
        for (int i = 0; i < 2; i++) {
            int r = i * 64 + sr0;
            size_t off = (size_t)r * lda + k0 + skq;
#pragma unroll
            for (int j = 0; j < NA; j++) pA[i][j] = *(const float4*)(Ap[j] + off);
            if constexpr (NM > 0) {
#pragma unroll
                for (int j = 0; j < NM; j++) pM[i][j] = *(const float4*)(Mp[j] + off);
            }
            pW[i] = *(const float4*)(W + (size_t)r * ldw + k0 + skq);
        }
    };

    loadAB(0);

    const int nc = K / KC;
    int buf = 0;
    for (int c = 0; c < nc; c++) {
        ull*   as = As2 + buf * AS2_BUFSTRIDE;
        float* ws = Wsm + buf * WSM_BUFSTRIDE;
        // stage regs -> smem[buf]
#pragma unroll
        for (int i = 0; i < 2; i++) {
            int r = i * 64 + sr0;
            float4 v = pA[i][0];
#pragma unroll
            for (int j = 1; j < NA; j++) {
                v.x += pA[i][j].x; v.y += pA[i][j].y;
                v.z += pA[i][j].z; v.w += pA[i][j].w;
            }
            if constexpr (NM > 0) {
                float4 m = pM[i][0];
#pragma unroll
                for (int j = 1; j < NM; j++) {
                    m.x += pM[i][j].x; m.y += pM[i][j].y;
                    m.z += pM[i][j].z; m.w += pM[i][j].w;
                }
                v.x *= m.x; v.y *= m.y; v.z *= m.z; v.w *= m.w;
            }
            as[(skq + 0) * 130 + r] = dup2(v.x);
            as[(skq + 1) * 130 + r] = dup2(v.y);
            as[(skq + 2) * 130 + r] = dup2(v.z);
            as[(skq + 3) * 130 + r] = dup2(v.w);
            ws[(skq + 0) * 132 + r] = pW[i].x;
            ws[(skq + 1) * 132 + r] = pW[i].y;
            ws[(skq + 2) * 132 + r] = pW[i].z;
            ws[(skq + 3) * 132 + r] = pW[i].w;
        }
        __syncthreads();

        if (c + 1 < nc) loadAB((c + 1) * KC);   // prefetch next chunk

#pragma unroll
        for (int k = 0; k < KC; k++) {
            const ull* arow = as + k * 130 + (w << 4);
            ulonglong2 bv = *(const ulonglong2*)(ws + k * 132 + 4 * l);
#pragma unroll
            for (int j = 0; j < 8; j++) {
                ulonglong2 av = *(const ulonglong2*)(arow + 2 * j);
                ffma2(acc[2 * j][0],     av.x, bv.x);
                ffma2(acc[2 * j][1],     av.x, bv.y);
                ffma2(acc[2 * j + 1][0], av.y, bv.x);
                ffma2(acc[2 * j + 1][1], av.y, bv.y);
            }
        }
        buf ^= 1;
        __syncthreads();
    }

    // epilogue: rows 16w+j, cols 4l..4l+3 (coalesced float4)
#pragma unroll
    for (int j = 0; j < 16; j++) {
        int row = (w << 4) + j;
        float4 o;
        o.x = __uint_as_float((unsigned)(acc[j][0] & 0xffffffffull));
        o.y = __uint_as_float((unsigned)(acc[j][0] >> 32));
        o.z = __uint_as_float((unsigned)(acc[j][1] & 0xffffffffull));
        o.w = __uint_as_float((unsigned)(acc[j][1] >> 32));
        *(float4*)(C + (size_t)row * ldc + 4 * l) = o;
    }
}

// ---------------------------------------------------------------------------
// The persistent kernel
// ---------------------------------------------------------------------------
__global__ __launch_bounds__(NTHR, 1) void enc_persistent(
    const int* __restrict__ ids, const int* __restrict__ xids,
    const float* __restrict__ wemb, const float* __restrict__ xemb,
    const float* __restrict__ Wsi, const float* __restrict__ Wsh,
    const float* __restrict__ b_bd, const float* __restrict__ vs,
    const float* __restrict__ Wmx1, const float* __restrict__ Wmh1,
    const float* __restrict__ Wih1, const float* __restrict__ Whh1,
    const float* __restrict__ b1,
    const float* __restrict__ Wmx2, const float* __restrict__ Wmh2,
    const float* __restrict__ Wih2, const float* __restrict__ Whh2,
    const float* __restrict__ b2,
    float* __restrict__ out)
{
    extern __shared__ __align__(16) char dynsmem[];
    ull*   As2 = (ull*)dynsmem;
    float* Wsm = (float*)(dynsmem + 2 * AS2_BUFSTRIDE * 8);
    __shared__ float red[8];

    const int blk = blockIdx.x;
    const int tid = threadIdx.x;
    const int gtid = blk * NTHR + tid;
    const int wid = tid >> 5, lane = tid & 31;
    const int gwarp = blk * 8 + wid;

    // ================= Prologue P1: states, u/wv/bdvs, embeds =================
    for (int i = gtid; i < Bz * Hz; i += GSTRIDE) {
        g_h1[i] = 0.0f; g_c1[i] = 0.0f; g_h2[i] = 0.0f; g_c2[i] = 0.0f;
    }
    for (int f = gwarp; f < FEATz; f += NBLK * 8) {        // u = Wsi^T vs
        float s = 0.0f;
        for (int m = lane; m < MIDz; m += 32) s += Wsi[(size_t)m * FEATz + f] * vs[m];
#pragma unroll
        for (int o = 16; o; o >>= 1) s += __shfl_xor_sync(~0u, s, o);
        if (lane == 0) g_u[f] = s;
    }
    for (int h = gwarp; h < Hz; h += NBLK * 8) {           // wv = Wsh^T vs
        float s = 0.0f;
        for (int m = lane; m < MIDz; m += 32) s += Wsh[(size_t)m * Hz + h] * vs[m];
#pragma unroll
        for (int o = 16; o; o >>= 1) s += __shfl_xor_sync(~0u, s, o);
        if (lane == 0) g_wv[h] = s;
    }
    if (blk == 0) {                                        // bdvs = b_bd · vs
        float sb = b_bd[tid] * vs[tid] + b_bd[tid + 256] * vs[tid + 256];
#pragma unroll
        for (int o = 16; o; o >>= 1) sb += __shfl_xor_sync(~0u, sb, o);
        if (lane == 0) red[wid] = sb;
        __syncthreads();
        if (tid == 0) {
            float s = 0.0f;
            for (int w2 = 0; w2 < 8; w2++) s += red[w2];
            g_bdvs = s;
        }
        __syncthreads();
    }
    {   // embed gather, float4 granularity (576 = 144 float4)
        const int Q = FEATz / 4;
        for (int i = gtid; i < Sz * Bz * Q; i += GSTRIDE) {
            int q = i % Q;
            int row = i / Q;
            int b = row & (Bz - 1);
            int t = row >> 7;
            int f = q * 4;
            float4 v;
            if (f < 512) v = *(const float4*)(wemb + (size_t)ids[b * Sz + t] * 512 + f);
            else         v = *(const float4*)(xemb + (size_t)xids[b * Sz + t] * 64 + (f - 512));
            *(float4*)(g_embeds + (size_t)row * FEATz + f) = v;
        }
    }
    gridbar();

    // ================= Prologue P2: zbxv + all x-dependent GEMMs ==============
    {   // zbxv[r] = embeds_row · u + bdvs  (warp per row)
        float bdv = g_bdvs;
        for (int r = gwarp; r < Sz * Bz; r += NBLK * 8) {
            const float* e = g_embeds + (size_t)r * FEATz;
            float s = 0.0f;
            for (int j = lane; j < FEATz; j += 32) s += e[j] * g_u[j];
#pragma unroll
            for (int o = 16; o; o >>= 1) s += __shfl_xor_sync(~0u, s, o);
            if (lane == 0) g_zbxv[r] = s + bdv;
        }
    }
    // 512 * (8 + 32) = 20480 tile items, K=576, 128-col tiles
    for (int it = blk; it < 20480; it += NBLK) {
        int t = it / 40, j = it % 40;
        const float* Aa[1] = { g_embeds + (size_t)t * Bz * FEATz };
        if (j < 8)
            gemm128<1, 0>(Aa, nullptr, FEATz,
                Wmx1 + (size_t)j * 128 * FEATz, FEATz, FEATz,
                g_mx1all + (size_t)t * Bz * Hz + j * 128, Hz, As2, Wsm);
        else
            gemm128<1, 0>(Aa, nullptr, FEATz,
                Wih1 + (size_t)(j - 8) * 128 * FEATz, FEATz, FEATz,
                g_zx1all + (size_t)t * Bz * G4Hz + (j - 8) * 128, G4Hz, As2, Wsm);
    }
    gridbar();

    // ============================ time loop ===================================
    for (int t = 0; t < Sz; t++) {

        // ---- Phase A: mh1 partials (8 col-tiles x K-split 8) + boundary s ----
        if (blk < 64) {
            int tile = blk >> 3, ks = blk & 7, ko = ks * 128;
            const float* Aa[1] = { g_h1 + ko };
            gemm128<1, 0>(Aa, nullptr, Hz,
                Wmh1 + (size_t)tile * 128 * Hz + ko, Hz, 128,
                g_mh1p[ks] + tile * 128, Hz, As2, Wsm);
        } else if (blk >= 128) {
            // s[r] = (h1_r · wv + zbxv[t,r] > 0) ; warp per row
            int r = (blk - 128) * 8 + wid;
            if (r < Bz) {
                const float* h1r = g_h1 + (size_t)r * Hz;
                float s = 0.0f;
#pragma unroll
                for (int i = 0; i < Hz / 32; i++)
                    s += h1r[lane + 32 * i] * g_wv[lane + 32 * i];
#pragma unroll
                for (int o = 16; o; o >>= 1) s += __shfl_xor_sync(~0u, s, o);
                if (lane == 0)
                    g_s[r] = (s + g_zbxv[t * Bz + r] > 0.0f) ? 1.0f : 0.0f;
            }
        }
        gridbar();

        const float flag = g_s[0];
        const bool doflag = (flag > 0.5f);
        if (blk == 0 && tid == 0) out[OUT_FLAGS + t] = flag;

        // ---- Phase B: p1 = (mx1all[t] .* Σ8 mh1p) @ Whh1^T, K-split 4 ----
        if (blk < 128) {
            int tile = blk >> 2, ks = blk & 3, ko = ks * 256;
            const float* Aa[1] = { g_mx1all + (size_t)t * Bz * Hz + ko };
            const float* Mp[8] = { g_mh1p[0] + ko, g_mh1p[1] + ko, g_mh1p[2] + ko,
                                   g_mh1p[3] + ko, g_mh1p[4] + ko, g_mh1p[5] + ko,
                                   g_mh1p[6] + ko, g_mh1p[7] + ko };
            gemm128<1, 8>(Aa, Mp, Hz,
                Whh1 + (size_t)tile * 128 * Hz + ko, Hz, 256,
                g_p1p[ks] + tile * 128, G4Hz, As2, Wsm);
        }
        gridbar();

        // ---- Phase C: gates1 (+ output write when flag==0) ----
        {
            const float* zx1 = g_zx1all + (size_t)t * Bz * G4Hz;
            for (int idx = gtid; idx < Bz * Hz; idx += GSTRIDE) {
                int b = idx >> 10, h = idx & (Hz - 1);
                size_t zi = (size_t)b * G4Hz + h;
                float vi = zx1[zi]        + b1[h]
                         + g_p1p[0][zi]        + g_p1p[1][zi]
                         + g_p1p[2][zi]        + g_p1p[3][zi];
                float vf = zx1[zi + Hz]   + b1[h + Hz]
                         + g_p1p[0][zi + Hz]   + g_p1p[1][zi + Hz]
                         + g_p1p[2][zi + Hz]   + g_p1p[3][zi + Hz];
                float vg = zx1[zi + 2*Hz] + b1[h + 2*Hz]
                         + g_p1p[0][zi + 2*Hz] + g_p1p[1][zi + 2*Hz]
                         + g_p1p[2][zi + 2*Hz] + g_p1p[3][zi + 2*Hz];
                float vo = zx1[zi + 3*Hz] + b1[h + 3*Hz]
                         + g_p1p[0][zi + 3*Hz] + g_p1p[1][zi + 3*Hz]
                         + g_p1p[2][zi + 3*Hz] + g_p1p[3][zi + 3*Hz];
                float c  = sigm(vf) * g_c1[idx] + sigm(vi) * tanhf(vg);
                float hn = sigm(vo) * tanhf(c);
                float sv = g_s[b];
                g_x2[idx] = hn * sv;
                g_h1[idx] = hn * (1.0f - sv);
                g_c1[idx] = c  * (1.0f - sv);
                if (!doflag)
                    out[(size_t)b * Sz * Hz + (size_t)t * Hz + h] = g_h2[idx];
            }
        }
        gridbar();   // end of C (end of step when flag==0)

        if (!doflag) continue;   // uniform across all blocks

        // ---- Phase D: mx2, zx2, mh2 (48 col-tiles x K-split 3 = 144 items) ----
        if (blk < 144) {
            int tile = blk / 3, seg = blk % 3;
            int ko = (seg == 0) ? 0 : (seg == 1 ? 352 : 688);
            int kl = (seg == 0) ? 352 : 336;
            const float* Aa[1];
            if (tile < 8) {
                Aa[0] = g_x2 + ko;
                gemm128<1, 0>(Aa, nullptr, Hz,
                    Wmx2 + (size_t)tile * 128 * Hz + ko, Hz, kl,
                    g_mx2p[seg] + tile * 128, Hz, As2, Wsm);
            } else if (tile < 40) {
                int z = tile - 8;
                Aa[0] = g_x2 + ko;
                gemm128<1, 0>(Aa, nullptr, Hz,
                    Wih2 + (size_t)z * 128 * Hz + ko, Hz, kl,
                    g_zx2p[seg] + z * 128, G4Hz, As2, Wsm);
            } else {
                int m2 = tile - 40;
                Aa[0] = g_h2 + ko;
                gemm128<1, 0>(Aa, nullptr, Hz,
                    Wmh2 + (size_t)m2 * 128 * Hz + ko, Hz, kl,
                    g_mh2p[seg] + m2 * 128, Hz, As2, Wsm);
            }
        }
        gridbar();

        // ---- Phase E: p2 = ((Σ3 mx2p) .* (Σ3 mh2p)) @ Whh2^T, K-split 4 ----
        if (blk < 128) {
            int tile = blk >> 2, ks = blk & 3, ko = ks * 256;
            const float* Aa[3] = { g_mx2p[0] + ko, g_mx2p[1] + ko, g_mx2p[2] + ko };
            const float* Mp[3] = { g_mh2p[0] + ko, g_mh2p[1] + ko, g_mh2p[2] + ko };
            gemm128<3, 3>(Aa, Mp, Hz,
                Whh2 + (size_t)tile * 128 * Hz + ko, Hz, 256,
                g_p2p[ks] + tile * 128, G4Hz, As2, Wsm);
        }
        gridbar();

        // ---- Phase F: gates2 + state update + output write ----
        for (int idx = gtid; idx < Bz * Hz; idx += GSTRIDE) {
            int b = idx >> 10, h = idx & (Hz - 1);
            size_t zi = (size_t)b * G4Hz + h;
            float vi = g_zx2p[0][zi]        + g_zx2p[1][zi]        + g_zx2p[2][zi]
                     + b2[h]
                     + g_p2p[0][zi]         + g_p2p[1][zi]
                     + g_p2p[2][zi]         + g_p2p[3][zi];
            float vf = g_zx2p[0][zi + Hz]   + g_zx2p[1][zi + Hz]   + g_zx2p[2][zi + Hz]
                     + b2[h + Hz]
                     + g_p2p[0][zi + Hz]    + g_p2p[1][zi + Hz]
                     + g_p2p[2][zi + Hz]    + g_p2p[3][zi + Hz];
            float vg = g_zx2p[0][zi + 2*Hz] + g_zx2p[1][zi + 2*Hz] + g_zx2p[2][zi + 2*Hz]
                     + b2[h + 2*Hz]
                     + g_p2p[0][zi + 2*Hz]  + g_p2p[1][zi + 2*Hz]
                     + g_p2p[2][zi + 2*Hz]  + g_p2p[3][zi + 2*Hz];
            float vo = g_zx2p[0][zi + 3*Hz] + g_zx2p[1][zi + 3*Hz] + g_zx2p[2][zi + 3*Hz]
                     + b2[h + 3*Hz]
                     + g_p2p[0][zi + 3*Hz]  + g_p2p[1][zi + 3*Hz]
                     + g_p2p[2][zi + 3*Hz]  + g_p2p[3][zi + 3*Hz];
            float c  = sigm(vf) * g_c2[idx] + sigm(vi) * tanhf(vg);
            float hn = sigm(vo) * tanhf(c);
            g_c2[idx] = c;
            g_h2[idx] = hn;
            out[(size_t)b * Sz * Hz + (size_t)t * Hz + h] = hn;
        }
        gridbar();
    }

    // ---------------- final state outputs ----------------
    for (int i = gtid; i < Bz * Hz; i += GSTRIDE) {
        out[OUT_H2 + i] = g_h2[i];
        out[OUT_C2 + i] = g_c2[i];
    }
}

// ---------------------------------------------------------------------------
// Launch: ONE kernel node, graph-capturable (dynamic smem for 50KB tiles)
// ---------------------------------------------------------------------------
extern "C" void kernel_launch(void* const* d_in, const int* in_sizes, int n_in,
                              void* d_out, int out_size) {
    const int*   ids   = (const int*)d_in[0];
    const int*   xids  = (const int*)d_in[1];
    const float* wemb  = (const float*)d_in[2];
    const float* xemb  = (const float*)d_in[3];
    const float* Wsi   = (const float*)d_in[4];
    const float* Wsh   = (const float*)d_in[5];
    const float* b_bd  = (const float*)d_in[6];
    const float* vs    = (const float*)d_in[7];
    const float* Wmx1  = (const float*)d_in[8];
    const float* Wmh1  = (const float*)d_in[9];
    const float* Wih1  = (const float*)d_in[10];
    const float* Whh1  = (const float*)d_in[11];
    const float* b1    = (const float*)d_in[12];
    const float* Wmx2  = (const float*)d_in[13];
    const float* Wmh2  = (const float*)d_in[14];
    const float* Wih2  = (const float*)d_in[15];
    const float* Whh2  = (const float*)d_in[16];
    const float* b2    = (const float*)d_in[17];
    float* out = (float*)d_out;

    cudaFuncSetAttribute(enc_persistent,
                         cudaFuncAttributeMaxDynamicSharedMemorySize, SMEM_DYN);

    enc_persistent<<<NBLK, NTHR, SMEM_DYN>>>(ids, xids, wemb, xemb,
                                             Wsi, Wsh, b_bd, vs,
                                             Wmx1, Wmh1, Wih1, Whh1, b1,
                                             Wmx2, Wmh2, Wih2, Whh2, b2,
                                             out);
}

// round 17
// speedup vs baseline: 2.8413x; 1.1846x over previous
#include <cuda_runtime.h>
#include <math.h>

// ---------------------------------------------------------------------------
// Problem dims
// ---------------------------------------------------------------------------
#define NBLK   148
#define NTHR   256
#define GSTRIDE (NBLK * NTHR)
#define Bz     128
#define Sz     512
#define Hz     1024
#define MIDz   512
#define FEATz  576
#define G4Hz   4096
#define KC     16

// Output layout: outs[B,S,H], h2f[1,B,H], c2f[1,B,H], flags[S]
#define OUT_H2    67108864
#define OUT_C2    67239936
#define OUT_FLAGS 67371008

typedef unsigned long long ull;

// ---------------------------------------------------------------------------
// Device-global scratch (allocation-free per harness rules)
// ---------------------------------------------------------------------------
__device__ __align__(16) float g_embeds[(size_t)Sz * Bz * FEATz];   // [t][b][f]
__device__ __align__(16) float g_mx1all[(size_t)Sz * Bz * Hz];      // X@Wmx1^T
__device__ __align__(16) float g_zx1all[(size_t)Sz * Bz * G4Hz];    // X@Wih1^T
__device__ __align__(16) float g_zbxv[Sz * Bz];                     // x·u + bdvs
__device__ __align__(16) float g_u[FEATz];                          // Wsi^T vs
__device__ __align__(16) float g_wv[Hz];                            // Wsh^T vs
__device__ float g_bdvs;

__device__ __align__(16) float g_h1[Bz * Hz];
__device__ __align__(16) float g_c1[Bz * Hz];
__device__ __align__(16) float g_h2[Bz * Hz];
__device__ __align__(16) float g_c2[Bz * Hz];
__device__ __align__(16) float g_x2c[Bz * Hz];          // compacted mLSTM2 input
__device__ __align__(16) float g_mh1p[4][Bz * Hz];      // compact rows
__device__ __align__(16) float g_p1p[4][Bz * G4Hz];     // compact rows
__device__ __align__(16) float g_mx2p[3][Bz * Hz];      // compact rows
__device__ __align__(16) float g_mh2p[3][Bz * Hz];      // compact rows
__device__ __align__(16) float g_zx2p[3][Bz * G4Hz];    // compact rows
__device__ __align__(16) float g_p2p[4][Bz * G4Hz];     // compact rows
__device__ __align__(16) float g_s[Bz];

// active-row bookkeeping
__device__ int g_act1[2][Bz], g_rinv1[2][Bz], g_n1[2];  // rows with h1 != 0 (per parity)
__device__ int g_act2[Bz], g_rinv2[Bz], g_n2;           // rows with s == 1 this step
// b2-only closed-form constants for inactive mLSTM2 rows
__device__ float g_kf[Hz], g_kig[Hz], g_ko[Hz];

// grid barrier state (zero-init; gen compared relatively, replay-safe)
__device__ unsigned g_bar_cnt;
__device__ volatile unsigned g_bar_gen;

__device__ __forceinline__ void gridbar() {
    __threadfence();               // release
    __syncthreads();
    if (threadIdx.x == 0) {
        unsigned gen = g_bar_gen;
        if (atomicAdd(&g_bar_cnt, 1u) == (unsigned)(NBLK - 1)) {
            g_bar_cnt = 0u;
            __threadfence();
            g_bar_gen = gen + 1u;
        } else {
            while (g_bar_gen == gen) { __nanosleep(32); }
        }
    }
    __syncthreads();
    __threadfence();               // acquire (CCTL.IVALL flushes L1D)
}

// ---------------------------------------------------------------------------
// Packed f32x2 helpers
// ---------------------------------------------------------------------------
__device__ __forceinline__ void ffma2(ull &acc, ull a, ull b) {
    asm("fma.rn.f32x2 %0, %1, %2, %0;" : "+l"(acc) : "l"(a), "l"(b));
}
__device__ __forceinline__ ull dup2(float x) {
    unsigned u = __float_as_uint(x);
    ull r;
    asm("mov.b64 %0, {%1, %1};" : "=l"(r) : "r"(u));
    return r;
}
__device__ __forceinline__ float sigm(float x) { return 1.0f / (1.0f + expf(-x)); }

// ---------------------------------------------------------------------------
// fp32 GEMM tile, 256 threads: C[rowbase:+64, 0:128] = A[rows,K] @ W[0:128,K]^T
//   A-operand = (Σ_{j<NA} Ap[j]) * (NM ? Σ_{j<NM} Mp[j] : 1)
//   GATHER: A rows come from glist[compact_row] (clamped to nrows-1);
//           Mp rows are always compact (clamped to 127).
// Warp w -> rows 8w..8w+7 ; lane l -> cols 4l..4l+3.
// A pre-duplicated (f32x2) in smem -> broadcast LDS.128; B one LDS.128/lane,
// conflict-free. Inner loop: 5 LDS + 16 FFMA2 per k, zero MOVs.
// ---------------------------------------------------------------------------
template<int NA, int NM, bool GATHER>
__device__ __forceinline__ void gemm64(
    const float* const* Ap, const float* const* Mp,
    const int* __restrict__ glist, int rowbase, int nrows, int lda,
    const float* __restrict__ W, int ldw, int K,
    float* __restrict__ C, int ldc,
    ull (*As)[KC][66], float (*Ws)[KC][132])
{
    const int tid = threadIdx.x;
    const int w = tid >> 5, l = tid & 31;

    ull acc[8][2];
#pragma unroll
    for (int i = 0; i < 8; i++) { acc[i][0] = 0ull; acc[i][1] = 0ull; }

    // A/M staging: thread -> local row sr (0..63), k sub-offset skq
    const int sr  = tid >> 2;
    const int skq = (tid & 3) * 4;
    int arow = rowbase + sr;
    int mrow = arow;
    if (mrow > 127) mrow = 127;                 // stay inside compact buffers
    if (GATHER) {
        int ci = rowbase + sr;
        if (ci >= nrows) ci = nrows - 1;        // duplicate last row (output unused)
        arow = glist[ci];
    } else {
        if (arow > 127) arow = 127;
    }
    // W staging: thread -> W row wr (0..127), 8 k's at offset wk
    const int wr = tid >> 1;
    const int wk = (tid & 1) * 8;

    float4 pA[NA];
    float4 pM[(NM > 0) ? NM : 1];
    float4 pW0, pW1;

    auto loadAB = [&](int k0) {
        size_t aoff = (size_t)arow * lda + k0 + skq;
#pragma unroll
        for (int j = 0; j < NA; j++) pA[j] = *(const float4*)(Ap[j] + aoff);
        if constexpr (NM > 0) {
            size_t moff = (size_t)mrow * lda + k0 + skq;
#pragma unroll
            for (int j = 0; j < NM; j++) pM[j] = *(const float4*)(Mp[j] + moff);
        }
        size_t woff = (size_t)wr * ldw + k0 + wk;
        pW0 = *(const float4*)(W + woff);
        pW1 = *(const float4*)(W + woff + 4);
    };

    loadAB(0);

    const int nc = K / KC;
    int buf = 0;
    for (int c = 0; c < nc; c++) {
        // combine + stage into smem[buf]
        {
            float4 v = pA[0];
#pragma unroll
            for (int j = 1; j < NA; j++) {
                v.x += pA[j].x; v.y += pA[j].y; v.z += pA[j].z; v.w += pA[j].w;
            }
            if constexpr (NM > 0) {
                float4 m = pM[0];
#pragma unroll
                for (int j = 1; j < NM; j++) {
                    m.x += pM[j].x; m.y += pM[j].y; m.z += pM[j].z; m.w += pM[j].w;
                }
                v.x *= m.x; v.y *= m.y; v.z *= m.z; v.w *= m.w;
            }
            As[buf][skq + 0][sr] = dup2(v.x);
            As[buf][skq + 1][sr] = dup2(v.y);
            As[buf][skq + 2][sr] = dup2(v.z);
            As[buf][skq + 3][sr] = dup2(v.w);
            Ws[buf][wk + 0][wr] = pW0.x; Ws[buf][wk + 1][wr] = pW0.y;
            Ws[buf][wk + 2][wr] = pW0.z; Ws[buf][wk + 3][wr] = pW0.w;
            Ws[buf][wk + 4][wr] = pW1.x; Ws[buf][wk + 5][wr] = pW1.y;
            Ws[buf][wk + 6][wr] = pW1.z; Ws[buf][wk + 7][wr] = pW1.w;
        }
        __syncthreads();

        if (c + 1 < nc) loadAB((c + 1) * KC);   // prefetch next chunk

#pragma unroll
        for (int k = 0; k < KC; k++) {
            const ull* arow_s = &As[buf][k][w << 3];
            ulonglong2 a01 = *(const ulonglong2*)(arow_s);
            ulonglong2 a23 = *(const ulonglong2*)(arow_s + 2);
            ulonglong2 a45 = *(const ulonglong2*)(arow_s + 4);
            ulonglong2 a67 = *(const ulonglong2*)(arow_s + 6);
            ulonglong2 bv  = *(const ulonglong2*)&Ws[buf][k][4 * l];
            ffma2(acc[0][0], a01.x, bv.x); ffma2(acc[0][1], a01.x, bv.y);
            ffma2(acc[1][0], a01.y, bv.x); ffma2(acc[1][1], a01.y, bv.y);
            ffma2(acc[2][0], a23.x, bv.x); ffma2(acc[2][1], a23.x, bv.y);
            ffma2(acc[3][0], a23.y, bv.x); ffma2(acc[3][1], a23.y, bv.y);
            ffma2(acc[4][0], a45.x, bv.x); ffma2(acc[4][1], a45.x, bv.y);
            ffma2(acc[5][0], a45.y, bv.x); ffma2(acc[5][1], a45.y, bv.y);
            ffma2(acc[6][0], a67.x, bv.x); ffma2(acc[6][1], a67.x, bv.y);
            ffma2(acc[7][0], a67.y, bv.x); ffma2(acc[7][1], a67.y, bv.y);
        }
        buf ^= 1;
        __syncthreads();
    }

    // epilogue: compact row = rowbase + 8w + j, cols 4l..4l+3
#pragma unroll
    for (int j = 0; j < 8; j++) {
        int row = rowbase + (w << 3) + j;
        float4 o;
        o.x = __uint_as_float((unsigned)(acc[j][0] & 0xffffffffull));
        o.y = __uint_as_float((unsigned)(acc[j][0] >> 32));
        o.z = __uint_as_float((unsigned)(acc[j][1] & 0xffffffffull));
        o.w = __uint_as_float((unsigned)(acc[j][1] >> 32));
        *(float4*)(C + (size_t)row * ldc + 4 * l) = o;
    }
}

// ---------------------------------------------------------------------------
// The persistent kernel
// ---------------------------------------------------------------------------
__global__ __launch_bounds__(NTHR, 1) void enc_persistent(
    const int* __restrict__ ids, const int* __restrict__ xids,
    const float* __restrict__ wemb, const float* __restrict__ xemb,
    const float* __restrict__ Wsi, const float* __restrict__ Wsh,
    const float* __restrict__ b_bd, const float* __restrict__ vs,
    const float* __restrict__ Wmx1, const float* __restrict__ Wmh1,
    const float* __restrict__ Wih1, const float* __restrict__ Whh1,
    const float* __restrict__ b1,
    const float* __restrict__ Wmx2, const float* __restrict__ Wmh2,
    const float* __restrict__ Wih2, const float* __restrict__ Whh2,
    const float* __restrict__ b2,
    float* __restrict__ out)
{
    __shared__ ull   As[2][KC][66];
    __shared__ float Ws[2][KC][132];
    __shared__ float red[8];

    const int blk = blockIdx.x;
    const int tid = threadIdx.x;
    const int gtid = blk * NTHR + tid;
    const int wid = tid >> 5, lane = tid & 31;
    const int gwarp = blk * 8 + wid;

    // ================= Prologue P1 =================
    for (int i = gtid; i < Bz * Hz; i += GSTRIDE) {
        g_h1[i] = 0.0f; g_c1[i] = 0.0f; g_h2[i] = 0.0f; g_c2[i] = 0.0f;
    }
    for (int f = gwarp; f < FEATz; f += NBLK * 8) {        // u = Wsi^T vs
        float s = 0.0f;
        for (int m = lane; m < MIDz; m += 32) s += Wsi[(size_t)m * FEATz + f] * vs[m];
#pragma unroll
        for (int o = 16; o; o >>= 1) s += __shfl_xor_sync(~0u, s, o);
        if (lane == 0) g_u[f] = s;
    }
    for (int h = gwarp; h < Hz; h += NBLK * 8) {           // wv = Wsh^T vs
        float s = 0.0f;
        for (int m = lane; m < MIDz; m += 32) s += Wsh[(size_t)m * Hz + h] * vs[m];
#pragma unroll
        for (int o = 16; o; o >>= 1) s += __shfl_xor_sync(~0u, s, o);
        if (lane == 0) g_wv[h] = s;
    }
    if (blk == 0) {                                        // bdvs = b_bd · vs
        float sb = b_bd[tid] * vs[tid] + b_bd[tid + 256] * vs[tid + 256];
#pragma unroll
        for (int o = 16; o; o >>= 1) sb += __shfl_xor_sync(~0u, sb, o);
        if (lane == 0) red[wid] = sb;
        __syncthreads();
        if (tid == 0) {
            float s = 0.0f;
            for (int w2 = 0; w2 < 8; w2++) s += red[w2];
            g_bdvs = s;
        }
        __syncthreads();
    }
    if (blk == 1) {                                        // b2-only constants
        for (int h = tid; h < Hz; h += NTHR) {
            g_kf[h]  = sigm(b2[h + Hz]);
            g_kig[h] = sigm(b2[h]) * tanhf(b2[h + 2 * Hz]);
            g_ko[h]  = sigm(b2[h + 3 * Hz]);
        }
    }
    if (blk == 2) {                                        // parity-0 lists: h1==0 -> empty
        if (tid < Bz) g_rinv1[0][tid] = -1;
        if (tid == 0) g_n1[0] = 0;
    }
    {   // embed gather, float4 granularity (576 = 144 float4)
        const int Q = FEATz / 4;
        for (int i = gtid; i < Sz * Bz * Q; i += GSTRIDE) {
            int q = i % Q;
            int row = i / Q;
            int b = row & (Bz - 1);
            int t = row >> 7;
            int f = q * 4;
            float4 v;
            if (f < 512) v = *(const float4*)(wemb + (size_t)ids[b * Sz + t] * 512 + f);
            else         v = *(const float4*)(xemb + (size_t)xids[b * Sz + t] * 64 + (f - 512));
            *(float4*)(g_embeds + (size_t)row * FEATz + f) = v;
        }
    }
    gridbar();

    // ================= Prologue P2: zbxv + all x-dependent GEMMs ==============
    {   // zbxv[r] = embeds_row · u + bdvs  (warp per row)
        float bdv = g_bdvs;
        for (int r = gwarp; r < Sz * Bz; r += NBLK * 8) {
            const float* e = g_embeds + (size_t)r * FEATz;
            float s = 0.0f;
            for (int j = lane; j < FEATz; j += 32) s += e[j] * g_u[j];
#pragma unroll
            for (int o = 16; o; o >>= 1) s += __shfl_xor_sync(~0u, s, o);
            if (lane == 0) g_zbxv[r] = s + bdv;
        }
    }
    // 512 steps * 2 rowtiles * (8 + 32) coltiles = 40960 items, K=576
    for (int it = blk; it < 40960; it += NBLK) {
        int t = it / 80, rem = it % 80;
        int rt = rem / 40, cj = rem % 40;
        const float* Aa[1] = { g_embeds + (size_t)t * Bz * FEATz };
        if (cj < 8)
            gemm64<1, 0, false>(Aa, nullptr, nullptr, rt * 64, Bz, FEATz,
                Wmx1 + (size_t)cj * 128 * FEATz, FEATz, FEATz,
                g_mx1all + (size_t)t * Bz * Hz + cj * 128, Hz, As, Ws);
        else
            gemm64<1, 0, false>(Aa, nullptr, nullptr, rt * 64, Bz, FEATz,
                Wih1 + (size_t)(cj - 8) * 128 * FEATz, FEATz, FEATz,
                g_zx1all + (size_t)t * Bz * G4Hz + (cj - 8) * 128, G4Hz, As, Ws);
    }
    gridbar();

    // ============================ time loop ===================================
    for (int t = 0; t < Sz; t++) {
        const int par = t & 1;
        const int n1 = g_n1[par];
        const int n1t = (n1 + 63) >> 6;
        const int* act1 = g_act1[par];

        // ---- Phase A: mh1 partials over active-h1 rows + boundary s ----
        {
            int items = n1t * 32;                       // rowtiles x 8ct x 4ks
            if (blk < items) {
                int rt = blk >> 5, rem = blk & 31;
                int ct = rem >> 2, ks = rem & 3, ko = ks * 256;
                const float* Aa[1] = { g_h1 + ko };
                gemm64<1, 0, true>(Aa, nullptr, act1, rt * 64, n1, Hz,
                    Wmh1 + (size_t)ct * 128 * Hz + ko, Hz, 256,
                    g_mh1p[ks] + ct * 128, Hz, As, Ws);
            } else if (blk >= 132) {
                // s[r] = (h1_r · wv + zbxv[t,r] > 0) ; warp per row
                int r = (blk - 132) * 8 + wid;
                if (r < Bz) {
                    const float* h1r = g_h1 + (size_t)r * Hz;
                    float s = 0.0f;
#pragma unroll
                    for (int i = 0; i < Hz / 32; i++)
                        s += h1r[lane + 32 * i] * g_wv[lane + 32 * i];
#pragma unroll
                    for (int o = 16; o; o >>= 1) s += __shfl_xor_sync(~0u, s, o);
                    if (lane == 0)
                        g_s[r] = (s + g_zbxv[t * Bz + r] > 0.0f) ? 1.0f : 0.0f;
                }
            }
        }
        gridbar();

        const float flag = g_s[0];
        const bool doflag = (flag > 0.5f);
        if (blk == 0 && tid == 0) out[OUT_FLAGS + t] = flag;

        // ---- Phase B: p1 GEMM (active rows) + list building (block 147) ----
        if (blk < 147) {
            int items = n1t * 128;                      // rowtiles x 32ct x 4ks
            for (int it2 = blk; it2 < items; it2 += 147) {
                int rt = it2 >> 7, rem = it2 & 127;
                int ct = rem >> 2, ks = rem & 3, ko = ks * 256;
                const float* Aa[1] = { g_mx1all + (size_t)t * Bz * Hz + ko };
                const float* Mp[4] = { g_mh1p[0] + ko, g_mh1p[1] + ko,
                                       g_mh1p[2] + ko, g_mh1p[3] + ko };
                gemm64<1, 4, true>(Aa, Mp, act1, rt * 64, n1, Hz,
                    Whh1 + (size_t)ct * 128 * Hz + ko, Hz, 256,
                    g_p1p[ks] + ct * 128, G4Hz, As, Ws);
            }
        } else if (tid == 0) {
            // build act2/rinv2 (s==1) and next-parity act1/rinv1 (s==0)
            int pn = (t + 1) & 1;
            int n2v = 0, n1n = 0;
            for (int b = 0; b < Bz; b++) {
                if (g_s[b] > 0.5f) {
                    g_act2[n2v] = b; g_rinv2[b] = n2v; n2v++;
                    g_rinv1[pn][b] = -1;
                } else {
                    g_rinv2[b] = -1;
                    g_act1[pn][n1n] = b; g_rinv1[pn][b] = n1n; n1n++;
                }
            }
            g_n2 = n2v; g_n1[pn] = n1n;
        }
        gridbar();

        const int n2 = g_n2;
        const int n2t = (n2 + 63) >> 6;

        // ---- Phase C: gates1 + h1/c1 update + x2c build (+ out when !flag) ----
        {
            const float* zx1 = g_zx1all + (size_t)t * Bz * G4Hz;
            for (int idx = gtid; idx < Bz * Hz; idx += GSTRIDE) {
                int b = idx >> 10, h = idx & (Hz - 1);
                int cr = g_rinv1[par][b];
                float pi = 0.f, pf = 0.f, pg = 0.f, po = 0.f;
                if (cr >= 0) {
                    size_t ci = (size_t)cr * G4Hz + h;
#pragma unroll
                    for (int q = 0; q < 4; q++) {
                        pi += g_p1p[q][ci];
                        pf += g_p1p[q][ci + Hz];
                        pg += g_p1p[q][ci + 2 * Hz];
                        po += g_p1p[q][ci + 3 * Hz];
                    }
                }
                size_t zi = (size_t)b * G4Hz + h;
                float vi = zx1[zi]          + b1[h]          + pi;
                float vf = zx1[zi + Hz]     + b1[h + Hz]     + pf;
                float vg = zx1[zi + 2 * Hz] + b1[h + 2 * Hz] + pg;
                float vo = zx1[zi + 3 * Hz] + b1[h + 3 * Hz] + po;
                float c  = sigm(vf) * g_c1[idx] + sigm(vi) * tanhf(vg);
                float hn = sigm(vo) * tanhf(c);
                float sv = g_s[b];
                g_h1[idx] = hn * (1.0f - sv);
                g_c1[idx] = c  * (1.0f - sv);
                if (doflag) {
                    int c2r = g_rinv2[b];
                    if (c2r >= 0) g_x2c[(size_t)c2r * Hz + h] = hn;
                } else {
                    out[(size_t)b * Sz * Hz + (size_t)t * Hz + h] = g_h2[idx];
                }
            }
        }
        gridbar();   // end of step when flag==0

        if (!doflag) continue;   // uniform across all blocks

        // ---- Phase D: mx2, zx2 (on x2c), mh2 (gather h2 by act2); K-split 3 ----
        {
            int Amx = n2t * 24, Azx = n2t * 96, Amh = n2t * 24;
            int items = Amx + Azx + Amh;
            for (int it2 = blk; it2 < items; it2 += NBLK) {
                int u = it2;
                int kind, rt, ct, seg;
                if (u < Amx)      { kind = 0; }
                else if (u < Amx + Azx) { kind = 1; u -= Amx; }
                else              { kind = 2; u -= Amx + Azx; }
                if (kind == 1) { rt = u / 96; int r2 = u % 96; ct = r2 / 3; seg = r2 % 3; }
                else           { rt = u / 24; int r2 = u % 24; ct = r2 / 3; seg = r2 % 3; }
                int ko = (seg == 0) ? 0 : (seg == 1 ? 352 : 688);
                int kl = (seg == 0) ? 352 : 336;
                if (kind == 0) {
                    const float* Aa[1] = { g_x2c + ko };
                    gemm64<1, 0, false>(Aa, nullptr, nullptr, rt * 64, n2, Hz,
                        Wmx2 + (size_t)ct * 128 * Hz + ko, Hz, kl,
                        g_mx2p[seg] + ct * 128, Hz, As, Ws);
                } else if (kind == 1) {
                    const float* Aa[1] = { g_x2c + ko };
                    gemm64<1, 0, false>(Aa, nullptr, nullptr, rt * 64, n2, Hz,
                        Wih2 + (size_t)ct * 128 * Hz + ko, Hz, kl,
                        g_zx2p[seg] + ct * 128, G4Hz, As, Ws);
                } else {
                    const float* Aa[1] = { g_h2 + ko };
                    gemm64<1, 0, true>(Aa, nullptr, g_act2, rt * 64, n2, Hz,
                        Wmh2 + (size_t)ct * 128 * Hz + ko, Hz, kl,
                        g_mh2p[seg] + ct * 128, Hz, As, Ws);
                }
            }
        }
        gridbar();

        // ---- Phase E: p2 = ((Σ3 mx2p) .* (Σ3 mh2p)) @ Whh2^T (compact rows) ----
        {
            int items = n2t * 128;                      // rowtiles x 32ct x 4ks
            for (int it2 = blk; it2 < items; it2 += NBLK) {
                int rt = it2 >> 7, rem = it2 & 127;
                int ct = rem >> 2, ks = rem & 3, ko = ks * 256;
                const float* Aa[3] = { g_mx2p[0] + ko, g_mx2p[1] + ko, g_mx2p[2] + ko };
                const float* Mp[3] = { g_mh2p[0] + ko, g_mh2p[1] + ko, g_mh2p[2] + ko };
                gemm64<3, 3, false>(Aa, Mp, nullptr, rt * 64, n2, Hz,
                    Whh2 + (size_t)ct * 128 * Hz + ko, Hz, 256,
                    g_p2p[ks] + ct * 128, G4Hz, As, Ws);
            }
        }
        gridbar();

        // ---- Phase F: gates2 (active) / b2-closed-form (inactive) + output ----
        for (int idx = gtid; idx < Bz * Hz; idx += GSTRIDE) {
            int b = idx >> 10, h = idx & (Hz - 1);
            int cr = g_rinv2[b];
            float c, hn;
            if (cr >= 0) {
                size_t ci = (size_t)cr * G4Hz + h;
                float vi = g_zx2p[0][ci]          + g_zx2p[1][ci]          + g_zx2p[2][ci]
                         + b2[h]
                         + g_p2p[0][ci]           + g_p2p[1][ci]
                         + g_p2p[2][ci]           + g_p2p[3][ci];
                float vf = g_zx2p[0][ci + Hz]     + g_zx2p[1][ci + Hz]     + g_zx2p[2][ci + Hz]
                         + b2[h + Hz]
                         + g_p2p[0][ci + Hz]      + g_p2p[1][ci + Hz]
                         + g_p2p[2][ci + Hz]      + g_p2p[3][ci + Hz];
                float vg = g_zx2p[0][ci + 2*Hz]   + g_zx2p[1][ci + 2*Hz]   + g_zx2p[2][ci + 2*Hz]
                         + b2[h + 2*Hz]
                         + g_p2p[0][ci + 2*Hz]    + g_p2p[1][ci + 2*Hz]
                         + g_p2p[2][ci + 2*Hz]    + g_p2p[3][ci + 2*Hz];
                float vo = g_zx2p[0][ci + 3*Hz]   + g_zx2p[1][ci + 3*Hz]   + g_zx2p[2][ci + 3*Hz]
                         + b2[h + 3*Hz]
                         + g_p2p[0][ci + 3*Hz]    + g_p2p[1][ci + 3*Hz]
                         + g_p2p[2][ci + 3*Hz]    + g_p2p[3][ci + 3*Hz];
                c  = sigm(vf) * g_c2[idx] + sigm(vi) * tanhf(vg);
                hn = sigm(vo) * tanhf(c);
            } else {
                c  = g_kf[h] * g_c2[idx] + g_kig[h];
                hn = g_ko[h] * tanhf(c);
            }
            g_c2[idx] = c;
            g_h2[idx] = hn;
            out[(size_t)b * Sz * Hz + (size_t)t * Hz + h] = hn;
        }
        gridbar();
    }

    // ---------------- final state outputs ----------------
    for (int i = gtid; i < Bz * Hz; i += GSTRIDE) {
        out[OUT_H2 + i] = g_h2[i];
        out[OUT_C2 + i] = g_c2[i];
    }
}

// ---------------------------------------------------------------------------
// Launch: ONE kernel node, graph-capturable
// ---------------------------------------------------------------------------
extern "C" void kernel_launch(void* const* d_in, const int* in_sizes, int n_in,
                              void* d_out, int out_size) {
    const int*   ids   = (const int*)d_in[0];
    const int*   xids  = (const int*)d_in[1];
    const float* wemb  = (const float*)d_in[2];
    const float* xemb  = (const float*)d_in[3];
    const float* Wsi   = (const float*)d_in[4];
    const float* Wsh   = (const float*)d_in[5];
    const float* b_bd  = (const float*)d_in[6];
    const float* vs    = (const float*)d_in[7];
    const float* Wmx1  = (const float*)d_in[8];
    const float* Wmh1  = (const float*)d_in[9];
    const float* Wih1  = (const float*)d_in[10];
    const float* Whh1  = (const float*)d_in[11];
    const float* b1    = (const float*)d_in[12];
    const float* Wmx2  = (const float*)d_in[13];
    const float* Wmh2  = (const float*)d_in[14];
    const float* Wih2  = (const float*)d_in[15];
    const float* Whh2  = (const float*)d_in[16];
    const float* b2    = (const float*)d_in[17];
    float* out = (float*)d_out;

    enc_persistent<<<NBLK, NTHR>>>(ids, xids, wemb, xemb,
                                   Wsi, Wsh, b_bd, vs,
                                   Wmx1, Wmh1, Wih1, Whh1, b1,
                                   Wmx2, Wmh2, Wih2, Whh2, b2,
                                   out);
}